// round 13
// baseline (speedup 1.0000x reference)
#include <cuda_runtime.h>
#include <cuda_fp16.h>
#include <cstdint>

#define BB 4
#define NN 256
#define HH 8

// ---------------- scratch ----------------
__device__ float g_WT[256 * 256];
__device__ float g_WodT[256 * 256];
__device__ float g_Wh[BB * NN * 256];
__device__ float g_od[BB * NN * 256];
__device__ float g_Whi[BB * NN * HH];
__device__ float g_Whj[BB * NN * HH];
__device__ float g_e[BB * HH * NN * NN];   // exp(leaky(logit)) (masked -> 0)

__device__ __forceinline__ uint32_t smem_u32(const void* p) {
    uint32_t a;
    asm("{ .reg .u64 t; cvta.to.shared.u64 t, %1; cvt.u32.u64 %0, t; }"
        : "=r"(a) : "l"(p));
    return a;
}
__device__ __forceinline__ uint32_t pkh2(float lo, float hi) {
    __half2 h = __floats2half2_rn(lo, hi);
    return *reinterpret_cast<uint32_t*>(&h);
}
__device__ __forceinline__ void mma16(float* c, uint32_t a0, uint32_t a1,
                                      uint32_t a2, uint32_t a3,
                                      uint32_t b0, uint32_t b1) {
    asm volatile(
        "mma.sync.aligned.m16n8k16.row.col.f32.f16.f16.f32 "
        "{%0,%1,%2,%3},{%4,%5,%6,%7},{%8,%9},{%0,%1,%2,%3};"
        : "+f"(c[0]), "+f"(c[1]), "+f"(c[2]), "+f"(c[3])
        : "r"(a0), "r"(a1), "r"(a2), "r"(a3), "r"(b0), "r"(b1));
}
#define LDSM4(r0, r1, r2, r3, addr) \
    asm volatile("ldmatrix.sync.aligned.m8n8.x4.shared.b16 {%0,%1,%2,%3},[%4];" \
                 : "=r"(r0), "=r"(r1), "=r"(r2), "=r"(r3) : "r"(addr))
#define STG_CS_F4(ptr, v) \
    asm volatile("st.global.cs.v4.f32 [%0], {%1,%2,%3,%4};" \
                 :: "l"(ptr), "f"((v).x), "f"((v).y), "f"((v).z), "f"((v).w) \
                 : "memory")

// ---------------- K0: transpose weights for k_node ----------------
__global__ __launch_bounds__(256) void k_transpose(
    const float* __restrict__ W_w, const float* __restrict__ Wod_w)
{
    int i = blockIdx.x * blockDim.x + threadIdx.x;
    int stride = gridDim.x * blockDim.x;
    for (int idx = i; idx < 65536; idx += stride) {
        int c = idx >> 8, t = idx & 255;
        g_WT[idx] = W_w[t * 256 + c];
        g_WodT[idx] = Wod_w[t * 256 + c];
    }
}

// ---------------- K1: Wh, od, Whi, Whj ----------------
__global__ __launch_bounds__(256) void k_node(
    const float* __restrict__ node_fea,
    const float* __restrict__ W_b, const float* __restrict__ Wod_b,
    const float* __restrict__ a1_w, const float* __restrict__ a2_w)
{
    __shared__ float nf_s[8][256];
    __shared__ float wh_s[8][256];
    int t = threadIdx.x;
    int b = blockIdx.y;
    int i0 = blockIdx.x * 8;

    for (int x = t; x < 8 * 256; x += 256) {
        int r = x >> 8, c = x & 255;
        int h = c >> 5, d = c & 31;
        nf_s[r][c] = node_fea[((b * HH + h) * NN + (i0 + r)) * 32 + d];
    }
    __syncthreads();

    float wh[8], odv[8];
    float wb = W_b[t], wob = Wod_b[t];
#pragma unroll
    for (int r = 0; r < 8; ++r) { wh[r] = wb; odv[r] = wob; }

#pragma unroll 4
    for (int c = 0; c < 256; ++c) {
        float wt = g_WT[c * 256 + t];
        float wo = g_WodT[c * 256 + t];
#pragma unroll
        for (int r = 0; r < 8; ++r) {
            float nv = nf_s[r][c];
            wh[r] = fmaf(nv, wt, wh[r]);
            odv[r] = fmaf(nv, wo, odv[r]);
        }
    }
#pragma unroll
    for (int r = 0; r < 8; ++r) {
        int row = b * NN + i0 + r;
        g_Wh[row * 256 + t] = wh[r];
        g_od[row * 256 + t] = odv[r];
        wh_s[r][t] = wh[r];
    }
    __syncthreads();

    int wid = t >> 5, lane = t & 31;
#pragma unroll 1
    for (int r = 0; r < 8; ++r) {
        float s1 = 0.f, s2 = 0.f;
#pragma unroll
        for (int k = 0; k < 8; ++k) {
            int c = lane + k * 32;
            float wv = wh_s[r][c];
            s1 = fmaf(wv, a1_w[wid * 256 + c], s1);
            s2 = fmaf(wv, a2_w[wid * 256 + c], s2);
        }
#pragma unroll
        for (int off = 16; off; off >>= 1) {
            s1 += __shfl_down_sync(0xffffffffu, s1, off);
            s2 += __shfl_down_sync(0xffffffffu, s2, off);
        }
        if (lane == 0) {
            int row = b * NN + i0 + r;
            g_Whi[row * 8 + wid] = s1;
            g_Whj[row * 8 + wid] = s2;
        }
    }
}

// ---------------- K2: fp16 mma edge kernel, B in registers -------------------
// 64j x 128n tiles (nh = n-half from block parity); warp tile 32j x 32n.
// smem: sA16 half[64*136] @0 (17408 B) | sB8 uint2[256] @17408 (2KB)
#define OFF_A16 0
#define OFF_B8 17408
#define EDGE_SMEM 19456
#define NTILES 8192
#define EGRID 296

__global__ __launch_bounds__(256, 2) void k_edge_mma(
    const float* __restrict__ edge_fea, const int* __restrict__ adj,
    const float* __restrict__ ae_w, const float* __restrict__ ae_b,
    const float* __restrict__ We_w, const float* __restrict__ We_b,
    float* __restrict__ edge_out)
{
    extern __shared__ char smc[];
    char* sA16 = smc + OFF_A16;
    uint2* sB8 = reinterpret_cast<uint2*>(smc + OFF_B8);
    uint32_t sA_u = smem_u32(sA16);

    int t = threadIdx.x;
    int w = t >> 5, lane = t & 31;
    int mg = w >> 2, ng = w & 3;             // mg: 2 j-groups, ng: 4 n-groups(32)
    int lr = lane >> 2, lc = lane & 3;

    int nh = blockIdx.x & 1;                 // parity-stable across u += EGRID

    uint32_t lds_base = sA_u + (uint32_t)(((mg * 32) + (lane & 15)) * 272 +
                                          (lane >> 4) * 16);

    // ---- B fragments -> registers, once (permuted-pair layout) ----
    uint4 Breg[8][2];
    {
        int rn = lane >> 2, plc = lane & 3;
#pragma unroll
        for (int s = 0; s < 8; ++s)
#pragma unroll
            for (int p = 0; p < 2; ++p) {
                int n0 = nh * 128 + (ng * 2 + p) * 16 + ((rn >> 1) << 2) + (rn & 1);
                int k0 = s * 16 + plc * 2;
                const float* w0 = We_w + n0 * 128 + k0;
                const float* w1 = We_w + (n0 + 2) * 128 + k0;
                Breg[s][p].x = pkh2(w0[0], w0[1]);
                Breg[s][p].y = pkh2(w0[8], w0[9]);
                Breg[s][p].z = pkh2(w1[0], w1[1]);
                Breg[s][p].w = pkh2(w1[8], w1[9]);
            }
    }
    if (t < 256) {   // ae logit columns as classic uint2 frags (smem, warp0 use)
        int s = t >> 5, l = t & 31;
        int rn = l >> 2, plc = l & 3;
        const float* src = ae_w + rn * 128 + s * 16 + plc * 2;
        uint2 pk;
        pk.x = pkh2(src[0], src[1]);
        pk.y = pkh2(src[8], src[9]);
        sB8[t] = pk;
    }
    __syncthreads();

    // tile u -> nh = u&1, j0 = ((u>>1)&3)<<6, i = (u>>3)&255, b = u>>11
    for (int u = blockIdx.x; u < NTILES; u += EGRID) {
        int b = u >> 11, i = (u >> 3) & 255, j0 = ((u >> 1) & 3) << 6;

        // ---- A load: 64j x 128k fp32 -> fp16 smem (8 float4 per thread)
#pragma unroll 2
        for (int it = 0; it < 8; ++it) {
            int idx = it * 256 + t;
            int h = idx >> 8, r = idx & 255, j = r >> 2, dq = r & 3;
            float4 v = *reinterpret_cast<const float4*>(
                edge_fea + ((((b * 8 + h) * NN + i) * NN) + j0 + j) * 16 + dq * 4);
            uint2 pk;
            pk.x = pkh2(v.x, v.y);
            pk.y = pkh2(v.z, v.w);
            *reinterpret_cast<uint2*>(sA16 + j * 272 + h * 32 + dq * 8) = pk;
        }
        __syncthreads();

        // ---- mainloop: only LDSM + MMA (B resident in regs)
        float c[2][4][4];
        float c8[2][4];
#pragma unroll
        for (int m = 0; m < 2; ++m) {
#pragma unroll
            for (int n = 0; n < 4; ++n)
#pragma unroll
                for (int q = 0; q < 4; ++q) c[m][n][q] = 0.f;
#pragma unroll
            for (int q = 0; q < 4; ++q) c8[m][q] = 0.f;
        }

#pragma unroll
        for (int s = 0; s < 8; ++s) {
            uint32_t A[2][4];
#pragma unroll
            for (int m = 0; m < 2; ++m)
                LDSM4(A[m][0], A[m][1], A[m][2], A[m][3],
                      lds_base + (uint32_t)(m * 4352 + s * 32));
#pragma unroll
            for (int m = 0; m < 2; ++m)
#pragma unroll
                for (int p = 0; p < 2; ++p) {
                    mma16(c[m][2 * p], A[m][0], A[m][1], A[m][2], A[m][3],
                          Breg[s][p].x, Breg[s][p].y);
                    mma16(c[m][2 * p + 1], A[m][0], A[m][1], A[m][2], A[m][3],
                          Breg[s][p].z, Breg[s][p].w);
                }
            if (nh == 0 && ng == 0) {
                uint2 B8 = sB8[s * 32 + lane];
#pragma unroll
                for (int m = 0; m < 2; ++m)
                    mma16(c8[m], A[m][0], A[m][1], A[m][2], A[m][3],
                          B8.x, B8.y);
            }
        }

        // ---- logits epilogue (nh==0, ng==0): store exp(leaky), masked -> 0
        if (nh == 0 && ng == 0) {
            int hp = lc * 2;
            float2 whi = *reinterpret_cast<const float2*>(
                g_Whi + (b * NN + i) * 8 + hp);
            float2 aeb = *reinterpret_cast<const float2*>(ae_b + hp);
            float bi0 = whi.x + aeb.x, bi1 = whi.y + aeb.y;
            const int* adjrow = adj + (b * NN + i) * NN;
#pragma unroll
            for (int m = 0; m < 2; ++m) {
#pragma unroll
                for (int half = 0; half < 2; ++half) {
                    int row = j0 + mg * 32 + m * 16 + lr + half * 8;
                    float2 whj = *reinterpret_cast<const float2*>(
                        g_Whj + (b * NN + row) * 8 + hp);
                    int av = adjrow[row];
                    float e0 = c8[m][half * 2] + bi0 + whj.x;
                    float e1 = c8[m][half * 2 + 1] + bi1 + whj.y;
                    e0 = (e0 > 0.f) ? e0 : 0.2f * e0;
                    e1 = (e1 > 0.f) ? e1 : 0.2f * e1;
                    float p0 = (av <= 0) ? 0.f : __expf(e0);
                    float p1 = (av <= 0) ? 0.f : __expf(e1);
                    g_e[((b * 8 + hp) * NN + i) * NN + row] = p0;
                    g_e[((b * 8 + hp + 1) * NN + i) * NN + row] = p1;
                }
            }
        }

        // ---- edge stores: float4 per thread, head-aligned
#pragma unroll
        for (int p = 0; p < 2; ++p) {
            int np = nh * 8 + ng * 2 + p;
            int h = np >> 1;
            int nb = (np << 4) + (lc << 2);          // global n base (0..255)
            int dd = nb & 31;
            float4 ob = *reinterpret_cast<const float4*>(
                g_od + (b * NN + i) * 256 + nb);
            float4 wbv = *reinterpret_cast<const float4*>(We_b + nb);
            ob.x += wbv.x; ob.y += wbv.y; ob.z += wbv.z; ob.w += wbv.w;
            int rowbase = ((b * 8 + h) * NN + i) * NN;
#pragma unroll
            for (int m = 0; m < 2; ++m) {
#pragma unroll
                for (int h2 = 0; h2 < 2; ++h2) {
                    int j = j0 + mg * 32 + m * 16 + lr + h2 * 8;
                    float4 od = *reinterpret_cast<const float4*>(
                        g_od + (b * NN + j) * 256 + nb);
                    float4 o;
                    o.x = c[m][2 * p][h2 * 2 + 0] + ob.x + od.x;
                    o.y = c[m][2 * p][h2 * 2 + 1] + ob.y + od.y;
                    o.z = c[m][2 * p + 1][h2 * 2 + 0] + ob.z + od.z;
                    o.w = c[m][2 * p + 1][h2 * 2 + 1] + ob.w + od.w;
                    float* dst = edge_out + (size_t)(rowbase + j) * 32 + dd;
                    STG_CS_F4(dst, o);
                }
            }
        }
        __syncthreads();   // sA16 consumed before next tile overwrites
    }
}

// ---------------- K3: normalize pre-exp'd scores + node_new ----------------
__global__ __launch_bounds__(256) void k_attn3(float* __restrict__ node_out)
{
    extern __shared__ float sm2[];
    float* Whs = sm2;            // [256][32]
    float* att = sm2 + 8192;     // [16][256]
    int t = threadIdx.x, w = t >> 5, lane = t & 31;
    int i0 = blockIdx.x << 4, h = blockIdx.y, b = blockIdx.z;

    float4* Wh4 = reinterpret_cast<float4*>(Whs);
    const float4* g4 = reinterpret_cast<const float4*>(g_Wh);
    for (int x = t; x < 2048; x += 256) {
        int j = x >> 3, dq = x & 7;
        Wh4[x] = g4[(b * NN + j) * 64 + (h << 3) + dq];
    }

    const float4* e4 = reinterpret_cast<const float4*>(g_e);
    float4 xv[4];
#pragma unroll
    for (int r = 0; r < 2; ++r) {
        int i = i0 + w + (r << 3);
        int idx = (((b << 3) + h) * NN + i) * 64 + (lane << 1);
        xv[2 * r] = e4[idx];
        xv[2 * r + 1] = e4[idx + 1];
    }
    __syncthreads();

#pragma unroll
    for (int r = 0; r < 2; ++r) {
        int il = w + (r << 3);
        float4 x0 = xv[2 * r], x1 = xv[2 * r + 1];
        float s = ((x0.x + x0.y) + (x0.z + x0.w)) +
                  ((x1.x + x1.y) + (x1.z + x1.w));
#pragma unroll
        for (int o = 16; o; o >>= 1)
            s += __shfl_xor_sync(0xffffffffu, s, o);
        float rinv = 1.0f / s;
        float4 y0 = {x0.x * rinv, x0.y * rinv, x0.z * rinv, x0.w * rinv};
        float4 y1 = {x1.x * rinv, x1.y * rinv, x1.z * rinv, x1.w * rinv};
        float4* arow = reinterpret_cast<float4*>(att + il * 256);
        arow[lane * 2] = y0;
        arow[lane * 2 + 1] = y1;
    }
    __syncthreads();

    // AV: split partial accumulators to halve the FMA dependency chain
    float a00 = 0.f, a01 = 0.f, a10 = 0.f, a11 = 0.f;
    const float4* a0 = reinterpret_cast<const float4*>(att + w * 256);
    const float4* a1 = reinterpret_cast<const float4*>(att + (w + 8) * 256);
#pragma unroll 4
    for (int jq = 0; jq < 64; ++jq) {
        int j = jq << 2;
        float w0 = Whs[j * 32 + lane];
        float w1 = Whs[(j + 1) * 32 + lane];
        float w2 = Whs[(j + 2) * 32 + lane];
        float w3 = Whs[(j + 3) * 32 + lane];
        float4 q0 = a0[jq];
        float4 q1 = a1[jq];
        a00 = fmaf(q0.x, w0, fmaf(q0.y, w1, a00));
        a01 = fmaf(q0.z, w2, fmaf(q0.w, w3, a01));
        a10 = fmaf(q1.x, w0, fmaf(q1.y, w1, a10));
        a11 = fmaf(q1.z, w2, fmaf(q1.w, w3, a11));
    }
    {
        int i = i0 + w;
        node_out[(((b << 3) + h) * NN + i) * 32 + lane] =
            (a00 + a01) + Whs[i * 32 + lane];
        i = i0 + w + 8;
        node_out[(((b << 3) + h) * NN + i) * 32 + lane] =
            (a10 + a11) + Whs[i * 32 + lane];
    }
}

// ---------------- launch ----------------
extern "C" void kernel_launch(void* const* d_in, const int* in_sizes, int n_in,
                              void* d_out, int out_size)
{
    const float* node_fea = (const float*)d_in[0];
    const float* edge_fea = (const float*)d_in[1];
    const int* adj = (const int*)d_in[2];
    const float* W_w = (const float*)d_in[3];
    const float* W_b = (const float*)d_in[4];
    const float* a1_w = (const float*)d_in[5];
    const float* a2_w = (const float*)d_in[6];
    const float* ae_w = (const float*)d_in[7];
    const float* ae_b = (const float*)d_in[8];
    const float* We_w = (const float*)d_in[9];
    const float* We_b = (const float*)d_in[10];
    const float* Wod_w = (const float*)d_in[11];
    const float* Wod_b = (const float*)d_in[12];

    float* out = (float*)d_out;
    float* node_out = out;                       // [B,H,N,DNO]
    float* edge_out = out + BB * HH * NN * 32;   // [B,H,N,N,DEO]

    cudaFuncSetAttribute(k_edge_mma, cudaFuncAttributeMaxDynamicSharedMemorySize,
                         EDGE_SMEM);
    cudaFuncSetAttribute(k_attn3, cudaFuncAttributeMaxDynamicSharedMemorySize,
                         49152);

    k_transpose<<<128, 256>>>(W_w, Wod_w);
    k_node<<<dim3(32, BB), 256>>>(node_fea, W_b, Wod_b, a1_w, a2_w);
    k_edge_mma<<<EGRID, 256, EDGE_SMEM>>>(edge_fea, adj, ae_w, ae_b, We_w, We_b,
                                          edge_out);
    k_attn3<<<dim3(16, HH, BB), 256, 49152>>>(node_out);
}

// round 14
// speedup vs baseline: 1.0600x; 1.0600x over previous
#include <cuda_runtime.h>
#include <cuda_fp16.h>
#include <cstdint>

#define BB 4
#define NN 256
#define HH 8

// ---------------- scratch ----------------
__device__ float g_WT[256 * 256];
__device__ float g_WodT[256 * 256];
__device__ float g_Wh[BB * NN * 256];
__device__ float g_od[BB * NN * 256];
__device__ float g_Whi[BB * NN * HH];
__device__ float g_Whj[BB * NN * HH];

__device__ __forceinline__ uint32_t smem_u32(const void* p) {
    uint32_t a;
    asm("{ .reg .u64 t; cvta.to.shared.u64 t, %1; cvt.u32.u64 %0, t; }"
        : "=r"(a) : "l"(p));
    return a;
}
__device__ __forceinline__ uint32_t pkh2(float lo, float hi) {
    __half2 h = __floats2half2_rn(lo, hi);
    return *reinterpret_cast<uint32_t*>(&h);
}
__device__ __forceinline__ void mma16(float* c, uint32_t a0, uint32_t a1,
                                      uint32_t a2, uint32_t a3,
                                      uint32_t b0, uint32_t b1) {
    asm volatile(
        "mma.sync.aligned.m16n8k16.row.col.f32.f16.f16.f32 "
        "{%0,%1,%2,%3},{%4,%5,%6,%7},{%8,%9},{%0,%1,%2,%3};"
        : "+f"(c[0]), "+f"(c[1]), "+f"(c[2]), "+f"(c[3])
        : "r"(a0), "r"(a1), "r"(a2), "r"(a3), "r"(b0), "r"(b1));
}
#define LDSM4(r0, r1, r2, r3, addr) \
    asm volatile("ldmatrix.sync.aligned.m8n8.x4.shared.b16 {%0,%1,%2,%3},[%4];" \
                 : "=r"(r0), "=r"(r1), "=r"(r2), "=r"(r3) : "r"(addr))

// ---------------- K0: transpose weights for k_node ----------------
__global__ __launch_bounds__(256) void k_transpose(
    const float* __restrict__ W_w, const float* __restrict__ Wod_w)
{
    int i = blockIdx.x * blockDim.x + threadIdx.x;
    int stride = gridDim.x * blockDim.x;
    for (int idx = i; idx < 65536; idx += stride) {
        int c = idx >> 8, t = idx & 255;
        g_WT[idx] = W_w[t * 256 + c];
        g_WodT[idx] = Wod_w[t * 256 + c];
    }
}

// ---------------- K1: Wh, od, Whi, Whj ----------------
__global__ __launch_bounds__(256) void k_node(
    const float* __restrict__ node_fea,
    const float* __restrict__ W_b, const float* __restrict__ Wod_b,
    const float* __restrict__ a1_w, const float* __restrict__ a2_w)
{
    __shared__ float nf_s[8][256];
    __shared__ float wh_s[8][256];
    int t = threadIdx.x;
    int b = blockIdx.y;
    int i0 = blockIdx.x * 8;

    for (int x = t; x < 8 * 256; x += 256) {
        int r = x >> 8, c = x & 255;
        int h = c >> 5, d = c & 31;
        nf_s[r][c] = node_fea[((b * HH + h) * NN + (i0 + r)) * 32 + d];
    }
    __syncthreads();

    float wh[8], odv[8];
    float wb = W_b[t], wob = Wod_b[t];
#pragma unroll
    for (int r = 0; r < 8; ++r) { wh[r] = wb; odv[r] = wob; }

#pragma unroll 4
    for (int c = 0; c < 256; ++c) {
        float wt = g_WT[c * 256 + t];
        float wo = g_WodT[c * 256 + t];
#pragma unroll
        for (int r = 0; r < 8; ++r) {
            float nv = nf_s[r][c];
            wh[r] = fmaf(nv, wt, wh[r]);
            odv[r] = fmaf(nv, wo, odv[r]);
        }
    }
#pragma unroll
    for (int r = 0; r < 8; ++r) {
        int row = b * NN + i0 + r;
        g_Wh[row * 256 + t] = wh[r];
        g_od[row * 256 + t] = odv[r];
        wh_s[r][t] = wh[r];
    }
    __syncthreads();

    int wid = t >> 5, lane = t & 31;
#pragma unroll 1
    for (int r = 0; r < 8; ++r) {
        float s1 = 0.f, s2 = 0.f;
#pragma unroll
        for (int k = 0; k < 8; ++k) {
            int c = lane + k * 32;
            float wv = wh_s[r][c];
            s1 = fmaf(wv, a1_w[wid * 256 + c], s1);
            s2 = fmaf(wv, a2_w[wid * 256 + c], s2);
        }
#pragma unroll
        for (int off = 16; off; off >>= 1) {
            s1 += __shfl_down_sync(0xffffffffu, s1, off);
            s2 += __shfl_down_sync(0xffffffffu, s2, off);
        }
        if (lane == 0) {
            int row = b * NN + i0 + r;
            g_Whi[row * 8 + wid] = s1;
            g_Whj[row * 8 + wid] = s2;
        }
    }
}

// ---------------- K2: fused edge GEMM + logits + softmax + AV ---------------
// unit q: nh = q&1 (block parity), i = (q>>1)&255, b = q>>9; inner jt = 0..3.
// nh==0 CTA accumulates exp(leaky(logits)) for all 8 heads in s_att, then
// does softmax-normalize + att@Wh + Wh and writes node_out for (b,i).
// smem: sB4 32KB @0 | sB8 2KB @32768 | sA16 17KB @34816 |
//       s_oib 512B @52224 | s_att 8x264 floats @52736  (total 61184)
#define OFF_B4 0
#define OFF_B8 32768
#define OFF_A16 34816
#define OFF_OIB 52224
#define OFF_ATT 52736
#define EDGE_SMEM 61184
#define NUNITS 2048
#define EGRID 444

__global__ __launch_bounds__(256, 3) void k_edge_fused(
    const float* __restrict__ edge_fea, const int* __restrict__ adj,
    const float* __restrict__ ae_w, const float* __restrict__ ae_b,
    const float* __restrict__ We_w, const float* __restrict__ We_b,
    float* __restrict__ edge_out, float* __restrict__ node_out)
{
    extern __shared__ char smc[];
    uint4* sB4 = reinterpret_cast<uint4*>(smc + OFF_B4);
    uint2* sB8 = reinterpret_cast<uint2*>(smc + OFF_B8);
    char* sA16 = smc + OFF_A16;
    float* s_oib = reinterpret_cast<float*>(smc + OFF_OIB);  // [128]
    float* s_att = reinterpret_cast<float*>(smc + OFF_ATT);  // [8][264]
    uint32_t sA_u = smem_u32(sA16);

    int t = threadIdx.x;
    int w = t >> 5, lane = t & 31;
    int mg = w >> 2, ng = w & 3;             // mg: 2 j-groups, ng: 4 n-groups
    int lr = lane >> 2, lc = lane & 3;

    int nh = blockIdx.x & 1;                 // parity-stable (EGRID even)

    uint32_t lds_base = sA_u + (uint32_t)((mg * 32 + (lane & 15)) * 272 +
                                          (lane >> 4) * 16);

    // ---- B pack (permuted pairs) for this n-half ----
    for (int x = t; x < 2048; x += 256) {
        int s = x >> 8, np = (x >> 5) & 7, l = x & 31;
        int rn = l >> 2, plc = l & 3;
        int n0 = nh * 128 + np * 16 + ((rn >> 1) << 2) + (rn & 1);
        int k0 = s * 16 + plc * 2;
        const float* w0 = We_w + n0 * 128 + k0;
        const float* w1 = We_w + (n0 + 2) * 128 + k0;
        uint4 pk;
        pk.x = pkh2(w0[0], w0[1]);
        pk.y = pkh2(w0[8], w0[9]);
        pk.z = pkh2(w1[0], w1[1]);
        pk.w = pkh2(w1[8], w1[9]);
        sB4[x] = pk;
    }
    {   // ae logit columns as classic uint2 frags
        int s = t >> 5, l = t & 31;
        int rn = l >> 2, plc = l & 3;
        const float* src = ae_w + rn * 128 + s * 16 + plc * 2;
        uint2 pk;
        pk.x = pkh2(src[0], src[1]);
        pk.y = pkh2(src[8], src[9]);
        sB8[t] = pk;
    }
    __syncthreads();

    for (int q = blockIdx.x; q < NUNITS; q += EGRID) {
        int i = (q >> 1) & 255, b = q >> 9;

        if (t < 128)
            s_oib[t] = g_od[(b * NN + i) * 256 + nh * 128 + t] +
                       We_b[nh * 128 + t];

#pragma unroll 1
        for (int jt = 0; jt < 4; ++jt) {
            int j0 = jt << 6;

            // ---- A load: 64j x 128k fp32 -> fp16 smem
#pragma unroll
            for (int it = 0; it < 8; ++it) {
                int idx = it * 256 + t;
                int h = idx >> 8, r = idx & 255, j = r >> 2, dq = r & 3;
                float4 v = *reinterpret_cast<const float4*>(
                    edge_fea + ((((b * 8 + h) * NN + i) * NN) + j0 + j) * 16 +
                    dq * 4);
                uint2 pk;
                pk.x = pkh2(v.x, v.y);
                pk.y = pkh2(v.z, v.w);
                *reinterpret_cast<uint2*>(sA16 + j * 272 + h * 32 + dq * 8) = pk;
            }
            __syncthreads();

            // ---- mainloop
            float c[2][4][4];
            float c8[2][4];
#pragma unroll
            for (int m = 0; m < 2; ++m) {
#pragma unroll
                for (int n = 0; n < 4; ++n)
#pragma unroll
                    for (int qq = 0; qq < 4; ++qq) c[m][n][qq] = 0.f;
#pragma unroll
                for (int qq = 0; qq < 4; ++qq) c8[m][qq] = 0.f;
            }

#pragma unroll
            for (int s = 0; s < 8; ++s) {
                uint32_t A[2][4];
#pragma unroll
                for (int m = 0; m < 2; ++m)
                    LDSM4(A[m][0], A[m][1], A[m][2], A[m][3],
                          lds_base + (uint32_t)(m * 4352 + s * 32));
                uint4 Bv[2];
#pragma unroll
                for (int p = 0; p < 2; ++p)
                    Bv[p] = sB4[(s * 8 + ng * 2 + p) * 32 + lane];
#pragma unroll
                for (int m = 0; m < 2; ++m)
#pragma unroll
                    for (int p = 0; p < 2; ++p) {
                        mma16(c[m][2 * p], A[m][0], A[m][1], A[m][2], A[m][3],
                              Bv[p].x, Bv[p].y);
                        mma16(c[m][2 * p + 1], A[m][0], A[m][1], A[m][2],
                              A[m][3], Bv[p].z, Bv[p].w);
                    }
                if (nh == 0 && ng == 0) {
                    uint2 B8 = sB8[s * 32 + lane];
#pragma unroll
                    for (int m = 0; m < 2; ++m)
                        mma16(c8[m], A[m][0], A[m][1], A[m][2], A[m][3],
                              B8.x, B8.y);
                }
            }

            // ---- logits -> s_att (nh==0, ng==0): exp(leaky), masked -> 0
            if (nh == 0 && ng == 0) {
                int hp = lc * 2;
                float2 whi = *reinterpret_cast<const float2*>(
                    g_Whi + (b * NN + i) * 8 + hp);
                float2 aeb = *reinterpret_cast<const float2*>(ae_b + hp);
                float bi0 = whi.x + aeb.x, bi1 = whi.y + aeb.y;
                const int* adjrow = adj + (b * NN + i) * NN;
#pragma unroll
                for (int m = 0; m < 2; ++m) {
#pragma unroll
                    for (int half = 0; half < 2; ++half) {
                        int row = j0 + mg * 32 + m * 16 + lr + half * 8;
                        float2 whj = *reinterpret_cast<const float2*>(
                            g_Whj + (b * NN + row) * 8 + hp);
                        int av = adjrow[row];
                        float e0 = c8[m][half * 2] + bi0 + whj.x;
                        float e1 = c8[m][half * 2 + 1] + bi1 + whj.y;
                        e0 = (e0 > 0.f) ? e0 : 0.2f * e0;
                        e1 = (e1 > 0.f) ? e1 : 0.2f * e1;
                        s_att[hp * 264 + row] = (av <= 0) ? 0.f : __expf(e0);
                        s_att[(hp + 1) * 264 + row] =
                            (av <= 0) ? 0.f : __expf(e1);
                    }
                }
            }

            // ---- edge stores
#pragma unroll
            for (int p = 0; p < 2; ++p) {
                int np = nh * 8 + ng * 2 + p;
                int h = np >> 1;
                int nb = (np << 4) + (lc << 2);
                int dd = nb & 31;
                float4 ob = *reinterpret_cast<const float4*>(
                    s_oib + ((ng * 2 + p) << 4) + (lc << 2));
                int rowbase = ((b * 8 + h) * NN + i) * NN;
#pragma unroll
                for (int m = 0; m < 2; ++m) {
#pragma unroll
                    for (int h2 = 0; h2 < 2; ++h2) {
                        int j = j0 + mg * 32 + m * 16 + lr + h2 * 8;
                        float4 od = *reinterpret_cast<const float4*>(
                            g_od + (b * NN + j) * 256 + nb);
                        float4 o;
                        o.x = c[m][2 * p][h2 * 2 + 0] + ob.x + od.x;
                        o.y = c[m][2 * p][h2 * 2 + 1] + ob.y + od.y;
                        o.z = c[m][2 * p + 1][h2 * 2 + 0] + ob.z + od.z;
                        o.w = c[m][2 * p + 1][h2 * 2 + 1] + ob.w + od.w;
                        *reinterpret_cast<float4*>(
                            edge_out + (size_t)(rowbase + j) * 32 + dd) = o;
                    }
                }
            }
            __syncthreads();   // sA16/s_att tile consumed before next jt
        }

        // ---- softmax normalize + AV + node_new (nh==0 CTAs; warp w = head)
        if (nh == 0) {
            int h = w;
            const float* arow = s_att + h * 264;
            float s = 0.f;
#pragma unroll
            for (int k2 = 0; k2 < 8; ++k2) s += arow[lane + k2 * 32];
#pragma unroll
            for (int o = 16; o; o >>= 1)
                s += __shfl_xor_sync(0xffffffffu, s, o);
            float rinv = 1.0f / s;

            const float* whb = g_Wh + (size_t)(b * NN) * 256 + h * 32 + lane;
            float a0 = 0.f, a1 = 0.f, a2 = 0.f, a3 = 0.f;
#pragma unroll 4
            for (int j = 0; j < 256; j += 4) {
                a0 = fmaf(arow[j], whb[(size_t)j * 256], a0);
                a1 = fmaf(arow[j + 1], whb[(size_t)(j + 1) * 256], a1);
                a2 = fmaf(arow[j + 2], whb[(size_t)(j + 2) * 256], a2);
                a3 = fmaf(arow[j + 3], whb[(size_t)(j + 3) * 256], a3);
            }
            float acc = (a0 + a1) + (a2 + a3);
            float self = g_Wh[(size_t)(b * NN + i) * 256 + h * 32 + lane];
            node_out[((b * 8 + h) * NN + i) * 32 + lane] = acc * rinv + self;
        }
        // next q's A-load __syncthreads orders these s_att reads before
        // the next logit writes; s_oib rewrite is pre-sync but disjoint.
        __syncthreads();
    }
}

// ---------------- launch ----------------
extern "C" void kernel_launch(void* const* d_in, const int* in_sizes, int n_in,
                              void* d_out, int out_size)
{
    const float* node_fea = (const float*)d_in[0];
    const float* edge_fea = (const float*)d_in[1];
    const int* adj = (const int*)d_in[2];
    const float* W_w = (const float*)d_in[3];
    const float* W_b = (const float*)d_in[4];
    const float* a1_w = (const float*)d_in[5];
    const float* a2_w = (const float*)d_in[6];
    const float* ae_w = (const float*)d_in[7];
    const float* ae_b = (const float*)d_in[8];
    const float* We_w = (const float*)d_in[9];
    const float* We_b = (const float*)d_in[10];
    const float* Wod_w = (const float*)d_in[11];
    const float* Wod_b = (const float*)d_in[12];

    float* out = (float*)d_out;
    float* node_out = out;                       // [B,H,N,DNO]
    float* edge_out = out + BB * HH * NN * 32;   // [B,H,N,N,DEO]

    cudaFuncSetAttribute(k_edge_fused, cudaFuncAttributeMaxDynamicSharedMemorySize,
                         EDGE_SMEM);

    k_transpose<<<128, 256>>>(W_w, Wod_w);
    k_node<<<dim3(32, BB), 256>>>(node_fea, W_b, Wod_b, a1_w, a2_w);
    k_edge_fused<<<EGRID, 256, EDGE_SMEM>>>(edge_fea, adj, ae_w, ae_b, We_w,
                                            We_b, edge_out, node_out);
}

// round 15
// speedup vs baseline: 1.1469x; 1.0820x over previous
#include <cuda_runtime.h>
#include <cuda_fp16.h>
#include <cstdint>

#define BB 4
#define NN 256
#define HH 8

// ---------------- scratch ----------------
__device__ float g_WT[256 * 256];
__device__ float g_WodT[256 * 256];
__device__ float g_Wh[BB * NN * 256];
__device__ float g_od[BB * NN * 256];
__device__ float g_Whi[BB * NN * HH];
__device__ float g_Whj[BB * NN * HH];
__device__ float g_e[BB * HH * NN * NN];   // exp(leaky(logit)) (masked -> 0)

__device__ __forceinline__ uint32_t smem_u32(const void* p) {
    uint32_t a;
    asm("{ .reg .u64 t; cvta.to.shared.u64 t, %1; cvt.u32.u64 %0, t; }"
        : "=r"(a) : "l"(p));
    return a;
}
__device__ __forceinline__ uint32_t pkh2(float lo, float hi) {
    __half2 h = __floats2half2_rn(lo, hi);
    return *reinterpret_cast<uint32_t*>(&h);
}
__device__ __forceinline__ void mma16(float* c, uint32_t a0, uint32_t a1,
                                      uint32_t a2, uint32_t a3,
                                      uint32_t b0, uint32_t b1) {
    asm volatile(
        "mma.sync.aligned.m16n8k16.row.col.f32.f16.f16.f32 "
        "{%0,%1,%2,%3},{%4,%5,%6,%7},{%8,%9},{%0,%1,%2,%3};"
        : "+f"(c[0]), "+f"(c[1]), "+f"(c[2]), "+f"(c[3])
        : "r"(a0), "r"(a1), "r"(a2), "r"(a3), "r"(b0), "r"(b1));
}
#define LDSM4(r0, r1, r2, r3, addr) \
    asm volatile("ldmatrix.sync.aligned.m8n8.x4.shared.b16 {%0,%1,%2,%3},[%4];" \
                 : "=r"(r0), "=r"(r1), "=r"(r2), "=r"(r3) : "r"(addr))
#define STG_CS_F4(ptr, v) \
    asm volatile("st.global.cs.v4.f32 [%0], {%1,%2,%3,%4};" \
                 :: "l"(ptr), "f"((v).x), "f"((v).y), "f"((v).z), "f"((v).w) \
                 : "memory")

// ---------------- K0: tiled transpose (coalesced both sides) ----------------
__global__ __launch_bounds__(256) void k_transpose(
    const float* __restrict__ W_w, const float* __restrict__ Wod_w)
{
    __shared__ float tl[32][33];
    int which = blockIdx.x >> 6;
    int tile = blockIdx.x & 63;
    const float* src = which ? Wod_w : W_w;
    float* dst = which ? g_WodT : g_WT;
    int tr = (tile >> 3) << 5;       // src row base
    int tc = (tile & 7) << 5;        // src col base
    int t = threadIdx.x;
    int lane = t & 31, r8 = t >> 5;
#pragma unroll
    for (int k = 0; k < 4; ++k)
        tl[r8 + 8 * k][lane] = src[(tr + r8 + 8 * k) * 256 + tc + lane];
    __syncthreads();
#pragma unroll
    for (int k = 0; k < 4; ++k)
        dst[(tc + r8 + 8 * k) * 256 + tr + lane] = tl[lane][r8 + 8 * k];
}

// ---------------- K1: Wh, od, Whi, Whj ----------------
__global__ __launch_bounds__(256) void k_node(
    const float* __restrict__ node_fea,
    const float* __restrict__ W_b, const float* __restrict__ Wod_b,
    const float* __restrict__ a1_w, const float* __restrict__ a2_w)
{
    __shared__ float nf_s[8][256];
    __shared__ float wh_s[8][256];
    int t = threadIdx.x;
    int b = blockIdx.y;
    int i0 = blockIdx.x * 8;

    for (int x = t; x < 8 * 256; x += 256) {
        int r = x >> 8, c = x & 255;
        int h = c >> 5, d = c & 31;
        nf_s[r][c] = node_fea[((b * HH + h) * NN + (i0 + r)) * 32 + d];
    }
    __syncthreads();

    float wh[8], odv[8];
    float wb = W_b[t], wob = Wod_b[t];
#pragma unroll
    for (int r = 0; r < 8; ++r) { wh[r] = wb; odv[r] = wob; }

#pragma unroll 4
    for (int c = 0; c < 256; ++c) {
        float wt = g_WT[c * 256 + t];
        float wo = g_WodT[c * 256 + t];
#pragma unroll
        for (int r = 0; r < 8; ++r) {
            float nv = nf_s[r][c];
            wh[r] = fmaf(nv, wt, wh[r]);
            odv[r] = fmaf(nv, wo, odv[r]);
        }
    }
#pragma unroll
    for (int r = 0; r < 8; ++r) {
        int row = b * NN + i0 + r;
        g_Wh[row * 256 + t] = wh[r];
        g_od[row * 256 + t] = odv[r];
        wh_s[r][t] = wh[r];
    }
    __syncthreads();

    int wid = t >> 5, lane = t & 31;
#pragma unroll 1
    for (int r = 0; r < 8; ++r) {
        float s1 = 0.f, s2 = 0.f;
#pragma unroll
        for (int k = 0; k < 8; ++k) {
            int c = lane + k * 32;
            float wv = wh_s[r][c];
            s1 = fmaf(wv, a1_w[wid * 256 + c], s1);
            s2 = fmaf(wv, a2_w[wid * 256 + c], s2);
        }
#pragma unroll
        for (int off = 16; off; off >>= 1) {
            s1 += __shfl_down_sync(0xffffffffu, s1, off);
            s2 += __shfl_down_sync(0xffffffffu, s2, off);
        }
        if (lane == 0) {
            int row = b * NN + i0 + r;
            g_Whi[row * 8 + wid] = s1;
            g_Whj[row * 8 + wid] = s2;
        }
    }
}

// ---------------- K2: fp16 mma edge kernel, 64j x 128n tiles, 3 CTA/SM ------
// smem bytes: sB4 uint4[2048] @0 (32KB) | sB8 uint2[256] @32768 (2KB) |
//             sA16 half[64*136] @34816 (17KB) | s_oib float[128] @52224
#define OFF_B4 0
#define OFF_B8 32768
#define OFF_A16 34816
#define OFF_OIB 52224
#define EDGE_SMEM 52736
#define NTILES 8192
#define EGRID 444

__global__ __launch_bounds__(256, 3) void k_edge_mma(
    const float* __restrict__ edge_fea, const int* __restrict__ adj,
    const float* __restrict__ ae_w, const float* __restrict__ ae_b,
    const float* __restrict__ We_w, const float* __restrict__ We_b,
    float* __restrict__ edge_out)
{
    extern __shared__ char smc[];
    uint4* sB4 = reinterpret_cast<uint4*>(smc + OFF_B4);
    uint2* sB8 = reinterpret_cast<uint2*>(smc + OFF_B8);
    char* sA16 = smc + OFF_A16;
    float* s_oib = reinterpret_cast<float*>(smc + OFF_OIB);
    uint32_t sA_u = smem_u32(sA16);

    int t = threadIdx.x;
    int w = t >> 5, lane = t & 31;
    int mg = w >> 2, ng = w & 3;
    int lr = lane >> 2, lc = lane & 3;

    int nh = blockIdx.x & 1;                 // EGRID even -> parity-stable

    uint32_t lds_base = sA_u + (uint32_t)((mg * 32 + (lane & 15)) * 272 +
                                          (lane >> 4) * 16);

    // ---- B pack (permuted pairs) for this n-half ----
    for (int x = t; x < 2048; x += 256) {
        int s = x >> 8, np = (x >> 5) & 7, l = x & 31;
        int rn = l >> 2, plc = l & 3;
        int n0 = nh * 128 + np * 16 + ((rn >> 1) << 2) + (rn & 1);
        int k0 = s * 16 + plc * 2;
        const float* w0 = We_w + n0 * 128 + k0;
        const float* w1 = We_w + (n0 + 2) * 128 + k0;
        uint4 pk;
        pk.x = pkh2(w0[0], w0[1]);
        pk.y = pkh2(w0[8], w0[9]);
        pk.z = pkh2(w1[0], w1[1]);
        pk.w = pkh2(w1[8], w1[9]);
        sB4[x] = pk;
    }
    if (t < 256) {   // ae logit columns as classic uint2 frags
        int s = t >> 5, l = t & 31;
        int rn = l >> 2, plc = l & 3;
        const float* src = ae_w + rn * 128 + s * 16 + plc * 2;
        uint2 pk;
        pk.x = pkh2(src[0], src[1]);
        pk.y = pkh2(src[8], src[9]);
        sB8[t] = pk;
    }

    // tile u -> b = u>>11, i = (u>>3)&255, j0 = ((u>>1)&3)<<6, nh = u&1
    for (int u = blockIdx.x; u < NTILES; u += EGRID) {
        int b = u >> 11, i = (u >> 3) & 255, j0 = ((u >> 1) & 3) << 6;

        // ---- A load: 64j x 128k fp32 -> fp16 smem
#pragma unroll 2
        for (int it = 0; it < 8; ++it) {
            int idx = it * 256 + t;
            int h = idx >> 8, r = idx & 255, j = r >> 2, dq = r & 3;
            float4 v = *reinterpret_cast<const float4*>(
                edge_fea + ((((b * 8 + h) * NN + i) * NN) + j0 + j) * 16 + dq * 4);
            uint2 pk;
            pk.x = pkh2(v.x, v.y);
            pk.y = pkh2(v.z, v.w);
            *reinterpret_cast<uint2*>(sA16 + j * 272 + h * 32 + dq * 8) = pk;
        }
        if (t < 128)
            s_oib[t] = g_od[(b * NN + i) * 256 + nh * 128 + t] +
                       We_b[nh * 128 + t];
        __syncthreads();

        // ---- mainloop
        float c[2][4][4];
        float c8[2][4];
#pragma unroll
        for (int a = 0; a < 2; ++a) {
#pragma unroll
            for (int n = 0; n < 4; ++n)
#pragma unroll
                for (int q = 0; q < 4; ++q) c[a][n][q] = 0.f;
#pragma unroll
            for (int q = 0; q < 4; ++q) c8[a][q] = 0.f;
        }

#pragma unroll
        for (int s = 0; s < 8; ++s) {
            uint32_t A[2][4];
#pragma unroll
            for (int m = 0; m < 2; ++m)
                LDSM4(A[m][0], A[m][1], A[m][2], A[m][3],
                      lds_base + (uint32_t)(m * 4352 + s * 32));
            uint4 Bv[2];
#pragma unroll
            for (int p = 0; p < 2; ++p)
                Bv[p] = sB4[(s * 8 + ng * 2 + p) * 32 + lane];
#pragma unroll
            for (int m = 0; m < 2; ++m)
#pragma unroll
                for (int p = 0; p < 2; ++p) {
                    mma16(c[m][2 * p], A[m][0], A[m][1], A[m][2], A[m][3],
                          Bv[p].x, Bv[p].y);
                    mma16(c[m][2 * p + 1], A[m][0], A[m][1], A[m][2], A[m][3],
                          Bv[p].z, Bv[p].w);
                }
            if (nh == 0 && ng == 0) {
                uint2 B8 = sB8[s * 32 + lane];
#pragma unroll
                for (int m = 0; m < 2; ++m)
                    mma16(c8[m], A[m][0], A[m][1], A[m][2], A[m][3],
                          B8.x, B8.y);
            }
        }

        // ---- logits epilogue (nh==0, ng==0): store exp(leaky), masked -> 0
        if (nh == 0 && ng == 0) {
            int hp = lc * 2;
            float2 whi = *reinterpret_cast<const float2*>(
                g_Whi + (b * NN + i) * 8 + hp);
            float2 aeb = *reinterpret_cast<const float2*>(ae_b + hp);
            float bi0 = whi.x + aeb.x, bi1 = whi.y + aeb.y;
            const int* adjrow = adj + (b * NN + i) * NN;
#pragma unroll
            for (int m = 0; m < 2; ++m) {
#pragma unroll
                for (int half = 0; half < 2; ++half) {
                    int row = j0 + mg * 32 + m * 16 + lr + half * 8;
                    float2 whj = *reinterpret_cast<const float2*>(
                        g_Whj + (b * NN + row) * 8 + hp);
                    int av = adjrow[row];
                    float e0 = c8[m][half * 2] + bi0 + whj.x;
                    float e1 = c8[m][half * 2 + 1] + bi1 + whj.y;
                    e0 = (e0 > 0.f) ? e0 : 0.2f * e0;
                    e1 = (e1 > 0.f) ? e1 : 0.2f * e1;
                    float p0 = (av <= 0) ? 0.f : __expf(e0);
                    float p1 = (av <= 0) ? 0.f : __expf(e1);
                    g_e[((b * 8 + hp) * NN + i) * NN + row] = p0;
                    g_e[((b * 8 + hp + 1) * NN + i) * NN + row] = p1;
                }
            }
        }

        // ---- edge stores
#pragma unroll
        for (int p = 0; p < 2; ++p) {
            int np = nh * 8 + ng * 2 + p;
            int h = np >> 1;
            int nb = (np << 4) + (lc << 2);
            int dd = nb & 31;
            float4 ob = *reinterpret_cast<const float4*>(
                s_oib + ((ng * 2 + p) << 4) + (lc << 2));
            int rowbase = ((b * 8 + h) * NN + i) * NN;
#pragma unroll
            for (int m = 0; m < 2; ++m) {
#pragma unroll
                for (int h2 = 0; h2 < 2; ++h2) {
                    int j = j0 + mg * 32 + m * 16 + lr + h2 * 8;
                    float4 od = *reinterpret_cast<const float4*>(
                        g_od + (b * NN + j) * 256 + nb);
                    float4 o;
                    o.x = c[m][2 * p][h2 * 2 + 0] + ob.x + od.x;
                    o.y = c[m][2 * p][h2 * 2 + 1] + ob.y + od.y;
                    o.z = c[m][2 * p + 1][h2 * 2 + 0] + ob.z + od.z;
                    o.w = c[m][2 * p + 1][h2 * 2 + 1] + ob.w + od.w;
                    float* dst = edge_out + (size_t)(rowbase + j) * 32 + dd;
                    STG_CS_F4(dst, o);
                }
            }
        }
        __syncthreads();   // s_oib / sA16 consumed before next tile overwrites
    }
}

// ---------------- K3: normalize pre-exp'd scores + node_new ----------------
// grid (16, 8, 4); block 256; i-block = 16 rows
__global__ __launch_bounds__(256) void k_attn3(float* __restrict__ node_out)
{
    extern __shared__ float sm2[];
    float* Whs = sm2;            // [256][32] = 32KB
    float* att = sm2 + 8192;     // [16][256] = 16KB
    int t = threadIdx.x, w = t >> 5, lane = t & 31;
    int i0 = blockIdx.x << 4, h = blockIdx.y, b = blockIdx.z;

    float4* Wh4 = reinterpret_cast<float4*>(Whs);
    const float4* g4 = reinterpret_cast<const float4*>(g_Wh);
    for (int x = t; x < 2048; x += 256) {
        int j = x >> 3, dq = x & 7;
        Wh4[x] = g4[(b * NN + j) * 64 + (h << 3) + dq];
    }

    // front-load all 4 LDG.128 (rows w and w+8)
    const float4* e4 = reinterpret_cast<const float4*>(g_e);
    float4 xv[4];
#pragma unroll
    for (int r = 0; r < 2; ++r) {
        int i = i0 + w + (r << 3);
        int idx = (((b << 3) + h) * NN + i) * 64 + (lane << 1);
        xv[2 * r] = e4[idx];
        xv[2 * r + 1] = e4[idx + 1];
    }
    __syncthreads();

#pragma unroll
    for (int r = 0; r < 2; ++r) {
        int il = w + (r << 3);
        float4 x0 = xv[2 * r], x1 = xv[2 * r + 1];
        float s = ((x0.x + x0.y) + (x0.z + x0.w)) +
                  ((x1.x + x1.y) + (x1.z + x1.w));
#pragma unroll
        for (int o = 16; o; o >>= 1)
            s += __shfl_xor_sync(0xffffffffu, s, o);
        float rinv = 1.0f / s;
        float4 y0 = {x0.x * rinv, x0.y * rinv, x0.z * rinv, x0.w * rinv};
        float4 y1 = {x1.x * rinv, x1.y * rinv, x1.z * rinv, x1.w * rinv};
        float4* arow = reinterpret_cast<float4*>(att + il * 256);
        arow[lane * 2] = y0;
        arow[lane * 2 + 1] = y1;
    }
    __syncthreads();

    float acc0 = 0.f, acc1 = 0.f;
    const float4* a0 = reinterpret_cast<const float4*>(att + w * 256);
    const float4* a1 = reinterpret_cast<const float4*>(att + (w + 8) * 256);
#pragma unroll 4
    for (int jq = 0; jq < 64; ++jq) {
        int j = jq << 2;
        float w0 = Whs[j * 32 + lane];
        float w1 = Whs[(j + 1) * 32 + lane];
        float w2 = Whs[(j + 2) * 32 + lane];
        float w3 = Whs[(j + 3) * 32 + lane];
        float4 q;
        q = a0[jq]; acc0 += q.x * w0 + q.y * w1 + q.z * w2 + q.w * w3;
        q = a1[jq]; acc1 += q.x * w0 + q.y * w1 + q.z * w2 + q.w * w3;
    }
    {
        int i = i0 + w;
        node_out[(((b << 3) + h) * NN + i) * 32 + lane] =
            acc0 + Whs[i * 32 + lane];
        i = i0 + w + 8;
        node_out[(((b << 3) + h) * NN + i) * 32 + lane] =
            acc1 + Whs[i * 32 + lane];
    }
}

// ---------------- launch ----------------
extern "C" void kernel_launch(void* const* d_in, const int* in_sizes, int n_in,
                              void* d_out, int out_size)
{
    const float* node_fea = (const float*)d_in[0];
    const float* edge_fea = (const float*)d_in[1];
    const int* adj = (const int*)d_in[2];
    const float* W_w = (const float*)d_in[3];
    const float* W_b = (const float*)d_in[4];
    const float* a1_w = (const float*)d_in[5];
    const float* a2_w = (const float*)d_in[6];
    const float* ae_w = (const float*)d_in[7];
    const float* ae_b = (const float*)d_in[8];
    const float* We_w = (const float*)d_in[9];
    const float* We_b = (const float*)d_in[10];
    const float* Wod_w = (const float*)d_in[11];
    const float* Wod_b = (const float*)d_in[12];

    float* out = (float*)d_out;
    float* node_out = out;                       // [B,H,N,DNO]
    float* edge_out = out + BB * HH * NN * 32;   // [B,H,N,N,DEO]

    cudaFuncSetAttribute(k_edge_mma, cudaFuncAttributeMaxDynamicSharedMemorySize,
                         EDGE_SMEM);
    cudaFuncSetAttribute(k_attn3, cudaFuncAttributeMaxDynamicSharedMemorySize,
                         49152);

    k_transpose<<<128, 256>>>(W_w, Wod_w);
    k_node<<<dim3(32, BB), 256>>>(node_fea, W_b, Wod_b, a1_w, a2_w);
    k_edge_mma<<<EGRID, 256, EDGE_SMEM>>>(edge_fea, adj, ae_w, ae_b, We_w, We_b,
                                          edge_out);
    k_attn3<<<dim3(16, HH, BB), 256, 49152>>>(node_out);
}